// round 7
// baseline (speedup 1.0000x reference)
#include <cuda_runtime.h>
#include <math.h>

#define Bsz 64
#define Lsz 200
#define BL  12800
#define Dd  256
#define Hh  512
#define H3  1536
#define Qq  1024
#define NQc 1024
#define WS_STRIDE 516
#define GRU_SMEM ((48*WS_STRIDE + 16*WS_STRIDE + 48*16*4) * sizeof(float))

typedef unsigned long long u64;
union F2U { u64 u; float2 f; };

// Packed fp32x2 FMA (sm_103a; ptxas never emits this from C++)
__device__ __forceinline__ u64 ffma2(u64 a, u64 b, u64 c) {
    u64 d;
    asm("fma.rn.f32x2 %0, %1, %2, %3;" : "=l"(d) : "l"(a), "l"(b), "l"(c));
    return d;
}
__device__ __forceinline__ u64 splat2(float x) {
    u64 d;
    asm("mov.b64 %0, {%1, %1};" : "=l"(d) : "f"(x));
    return d;
}

__device__ __align__(16) float g_x[(size_t)BL * 512];
__device__ __align__(16) float g_xg[(size_t)BL * H3];
__device__ __align__(16) float g_gru[(size_t)BL * Hh];
__device__ __align__(16) float g_h[2][Bsz * Hh];
__device__ __align__(16) float g_M2[(size_t)Qq * Hh];
__device__ float g_cvec[Qq];
__device__ float g_mvals[BL];
__device__ float g_mse, g_creg, g_cnt;
__device__ unsigned g_bar_count;
__device__ volatile unsigned g_bar_gen;

__global__ void init_kernel() {
    int idx = blockIdx.x * 256 + threadIdx.x;
    if (idx < Bsz * Hh) g_h[0][idx] = 0.0f;
    if (idx == 0) { g_mse = 0.f; g_creg = 0.f; g_cnt = 0.f; g_bar_count = 0u; g_bar_gen = 0u; }
}

__global__ void embed_kernel(const int* __restrict__ qd, const int* __restrict__ qad,
                             const int* __restrict__ pidd,
                             const float* __restrict__ q_emb, const float* __restrict__ qa_emb,
                             const float* __restrict__ q_ed, const float* __restrict__ qa_ed,
                             const float* __restrict__ dparm) {
    int bt = blockIdx.x;
    int q = qd[bt];
    int qa = (qad[bt] - q) / NQc;
    float pid = dparm[pidd[bt]];
    int tid = threadIdx.x;
    if (tid == 0) atomicAdd(&g_creg, pid * pid);
    const float4* qe   = (const float4*)(q_emb  + (size_t)q  * Dd);
    const float4* qae  = (const float4*)(qa_emb + (size_t)qa * Dd);
    const float4* qed  = (const float4*)(q_ed   + (size_t)q  * Dd);
    const float4* qaed = (const float4*)(qa_ed  + (size_t)qa * Dd);
    float4* xo = (float4*)(g_x + (size_t)bt * 512);
    if (tid < 64) {
        float4 a = qae[tid], b = qe[tid], c = qaed[tid], r;
        r.x = a.x + b.x + pid * c.x; r.y = a.y + b.y + pid * c.y;
        r.z = a.z + b.z + pid * c.z; r.w = a.w + b.w + pid * c.w;
        xo[tid] = r;
    } else {
        int j = tid - 64;
        float4 b = qe[j], d = qed[j], r;
        r.x = b.x + pid * d.x; r.y = b.y + pid * d.y;
        r.z = b.z + pid * d.z; r.w = b.w + pid * d.w;
        xo[64 + j] = r;
    }
}

// g_xg[12800,1536] = g_x[12800,512] @ w_ih[1536,512]^T + b_ih   (f32x2 inner)
__global__ __launch_bounds__(256, 2) void sgemm128_bt(const float* __restrict__ B,
                                                      const float* __restrict__ bias) {
    const int N = H3, K = 512;
    __shared__ float As[16 * 128];
    __shared__ float Bs[16 * 128];
    const int m0 = blockIdx.y * 128, n0 = blockIdx.x * 128;
    const int tid = threadIdx.x, tx = tid & 15, ty = tid >> 4;
    u64 acc2[8][4];
#pragma unroll
    for (int i = 0; i < 8; ++i)
#pragma unroll
        for (int j = 0; j < 4; ++j) acc2[i][j] = 0ull;
    for (int kt = 0; kt < K; kt += 16) {
#pragma unroll
        for (int jj = 0; jj < 2; ++jj) {
            int idx = tid + jj * 256;
            int m = idx & 127, kq = idx >> 7;
            float4 va = *(const float4*)&g_x[(size_t)(m0 + m) * K + kt + kq * 4];
            As[(kq*4+0)*128 + m] = va.x; As[(kq*4+1)*128 + m] = va.y;
            As[(kq*4+2)*128 + m] = va.z; As[(kq*4+3)*128 + m] = va.w;
            float4 vb = *(const float4*)&B[(size_t)(n0 + m) * K + kt + kq * 4];
            Bs[(kq*4+0)*128 + m] = vb.x; Bs[(kq*4+1)*128 + m] = vb.y;
            Bs[(kq*4+2)*128 + m] = vb.z; Bs[(kq*4+3)*128 + m] = vb.w;
        }
        __syncthreads();
#pragma unroll
        for (int k = 0; k < 16; ++k) {
            float4 a0 = *(float4*)&As[k*128 + ty*8];
            float4 a1 = *(float4*)&As[k*128 + ty*8 + 4];
            ulonglong2 bq0 = *(ulonglong2*)&Bs[k*128 + tx*8];
            ulonglong2 bq1 = *(ulonglong2*)&Bs[k*128 + tx*8 + 4];
            u64 b2[4] = {bq0.x, bq0.y, bq1.x, bq1.y};
            float av[8] = {a0.x,a0.y,a0.z,a0.w,a1.x,a1.y,a1.z,a1.w};
            u64 a2[8];
#pragma unroll
            for (int i = 0; i < 8; ++i) a2[i] = splat2(av[i]);
#pragma unroll
            for (int i = 0; i < 8; ++i)
#pragma unroll
                for (int j = 0; j < 4; ++j) acc2[i][j] = ffma2(a2[i], b2[j], acc2[i][j]);
        }
        __syncthreads();
    }
    float bv0[8];
#pragma unroll
    for (int j = 0; j < 8; ++j) bv0[j] = bias[n0 + tx*8 + j];
#pragma unroll
    for (int i = 0; i < 8; ++i) {
        size_t row = (size_t)(m0 + ty*8 + i) * N + n0 + tx*8;
        float o[8];
#pragma unroll
        for (int j = 0; j < 4; ++j) {
            F2U v; v.u = acc2[i][j];
            o[2*j]   = v.f.x + bv0[2*j];
            o[2*j+1] = v.f.y + bv0[2*j+1];
        }
        *(float4*)&g_xg[row]     = make_float4(o[0], o[1], o[2], o[3]);
        *(float4*)&g_xg[row + 4] = make_float4(o[4], o[5], o[6], o[7]);
    }
}

// g_M2[1024,512] = matrix[1024,1024] @ fc_w[1024,512]
__global__ __launch_bounds__(256, 4) void sgemm64_nn(const float* __restrict__ A,
                                                     const float* __restrict__ B) {
    const int N = Hh, K = Qq;
    __shared__ float As[16 * 64];
    __shared__ float Bs[16 * 64];
    const int m0 = blockIdx.y * 64, n0 = blockIdx.x * 64;
    const int tid = threadIdx.x, tx = tid & 15, ty = tid >> 4;
    float acc[4][4];
#pragma unroll
    for (int i = 0; i < 4; ++i)
#pragma unroll
        for (int j = 0; j < 4; ++j) acc[i][j] = 0.0f;
    for (int kt = 0; kt < K; kt += 16) {
        int m = tid & 63, kq = tid >> 6;
        float4 va = *(const float4*)&A[(size_t)(m0 + m) * K + kt + kq * 4];
        As[(kq*4+0)*64 + m] = va.x; As[(kq*4+1)*64 + m] = va.y;
        As[(kq*4+2)*64 + m] = va.z; As[(kq*4+3)*64 + m] = va.w;
        int kk = tid >> 4, nq = tid & 15;
        *(float4*)&Bs[kk*64 + nq*4] = *(const float4*)&B[(size_t)(kt + kk) * N + n0 + nq * 4];
        __syncthreads();
#pragma unroll
        for (int k = 0; k < 16; ++k) {
            float4 a = *(float4*)&As[k*64 + ty*4];
            float4 b = *(float4*)&Bs[k*64 + tx*4];
            float av[4] = {a.x,a.y,a.z,a.w};
            float bv[4] = {b.x,b.y,b.z,b.w};
#pragma unroll
            for (int i = 0; i < 4; ++i)
#pragma unroll
                for (int j = 0; j < 4; ++j) acc[i][j] += av[i] * bv[j];
        }
        __syncthreads();
    }
#pragma unroll
    for (int i = 0; i < 4; ++i) {
        float4 o; o.x = acc[i][0]; o.y = acc[i][1]; o.z = acc[i][2]; o.w = acc[i][3];
        *(float4*)&g_M2[(size_t)(m0 + ty*4 + i) * N + n0 + tx*4] = o;
    }
}

__global__ void cvec_kernel(const float* __restrict__ matrix, const float* __restrict__ fc_b) {
    int row = blockIdx.x, tid = threadIdx.x;
    float4 a = ((const float4*)(matrix + (size_t)row * Qq))[tid];
    float4 b = ((const float4*)fc_b)[tid];
    float s = a.x*b.x + a.y*b.y + a.z*b.z + a.w*b.w;
#pragma unroll
    for (int o = 16; o > 0; o >>= 1) s += __shfl_down_sync(0xffffffffu, s, o);
    __shared__ float red[8];
    if ((tid & 31) == 0) red[tid >> 5] = s;
    __syncthreads();
    if (tid == 0) {
        float t = 0.f;
#pragma unroll
        for (int w = 0; w < 8; ++w) t += red[w];
        g_cvec[row] = t;
    }
}

// Persistent GRU: 128 blocks x 256 thr, block = 16b x 16j, w slice in smem.
__global__ __launch_bounds__(256, 1) void gru_kernel(const float* __restrict__ w_hh,
                                                     const float* __restrict__ b_hh) {
    extern __shared__ float sm[];
    float* ws = sm;
    float* hs = ws + 48 * WS_STRIDE;
    float* ps = hs + 16 * WS_STRIDE;
    const int tid = threadIdx.x;
    const int bg = blockIdx.x & 3, jg = blockIdx.x >> 2;
    const int b0 = bg * 16, j0 = jg * 16;
    for (int i = tid; i < 48 * 128; i += 256) {
        int row = i >> 7, k4 = (i & 127) * 4;
        int jj = row / 3, g = row % 3;
        *(float4*)&ws[row * WS_STRIDE + k4] =
            *(const float4*)&w_hh[((size_t)(g * Hh + j0 + jj)) * Hh + k4];
    }
    const int tb = tid & 3, tjg = (tid >> 2) & 15, ks = tid >> 6;
    const int cbb = tid & 15, cjj = tid >> 4;
    const int cb = b0 + cbb, cj = j0 + cjj;
    const float bh0 = b_hh[0 * Hh + cj];
    const float bh1 = b_hh[1 * Hh + cj];
    const float bh2 = b_hh[2 * Hh + cj];
    for (int t = 0; t < Lsz; ++t) {
        const float* hsrc = g_h[t & 1];
        for (int i = tid; i < 16 * 128; i += 256) {
            int bb = i >> 7, k4 = (i & 127) * 4;
            float4 v = __ldcg((const float4*)&hsrc[(b0 + bb) * Hh + k4]);
            *(float4*)&hs[bb * WS_STRIDE + k4] = v;
        }
        __syncthreads();
        u64 acc2[3][4];
#pragma unroll
        for (int g = 0; g < 3; ++g)
#pragma unroll
            for (int i = 0; i < 4; ++i) acc2[g][i] = 0ull;
        const int kb = ks * 128;
#pragma unroll 4
        for (int k = kb; k < kb + 128; k += 4) {
            ulonglong2 h2[4];
#pragma unroll
            for (int i = 0; i < 4; ++i)
                h2[i] = *(ulonglong2*)&hs[(i*4 + tb) * WS_STRIDE + k];
#pragma unroll
            for (int g = 0; g < 3; ++g) {
                ulonglong2 w2 = *(ulonglong2*)&ws[(tjg*3 + g) * WS_STRIDE + k];
#pragma unroll
                for (int i = 0; i < 4; ++i) {
                    acc2[g][i] = ffma2(h2[i].x, w2.x, acc2[g][i]);
                    acc2[g][i] = ffma2(h2[i].y, w2.y, acc2[g][i]);
                }
            }
        }
#pragma unroll
        for (int g = 0; g < 3; ++g)
#pragma unroll
            for (int i = 0; i < 4; ++i) {
                F2U v; v.u = acc2[g][i];
                ps[((tjg*3 + g) * 16 + (i*4 + tb)) * 4 + ks] = v.f.x + v.f.y;
            }
        __syncthreads();
        {
            const float* pp0 = &ps[((cjj*3 + 0) * 16 + cbb) * 4];
            const float* pp1 = &ps[((cjj*3 + 1) * 16 + cbb) * 4];
            const float* pp2 = &ps[((cjj*3 + 2) * 16 + cbb) * 4];
            float hg0 = pp0[0] + pp0[1] + pp0[2] + pp0[3] + bh0;
            float hg1 = pp1[0] + pp1[1] + pp1[2] + pp1[3] + bh1;
            float hg2 = pp2[0] + pp2[1] + pp2[2] + pp2[3] + bh2;
            const float* xgp = &g_xg[((size_t)cb * Lsz + t) * H3];
            float r = 1.0f / (1.0f + expf(-(xgp[cj] + hg0)));
            float z = 1.0f / (1.0f + expf(-(xgp[Hh + cj] + hg1)));
            float n = tanhf(xgp[2*Hh + cj] + r * hg2);
            float hprev = hs[cbb * WS_STRIDE + cj];
            float hnew = (1.0f - z) * n + z * hprev;
            g_h[(t + 1) & 1][cb * Hh + cj] = hnew;
            g_gru[((size_t)cb * Lsz + t) * Hh + cj] = hnew;
        }
        __syncthreads();
        if (tid == 0) {
            __threadfence();
            unsigned gen = g_bar_gen;
            if (atomicAdd(&g_bar_count, 1u) == 127u) {
                g_bar_count = 0u;
                __threadfence();
                g_bar_gen = gen + 1u;
            } else {
                while (g_bar_gen == gen) {}
                __threadfence();
            }
        }
        __syncthreads();
    }
}

__global__ void master_kernel(const int* __restrict__ qd) {
    int bt = blockIdx.x, tid = threadIdx.x;
    int k = qd[bt] - 1;
    float4 a = ((const float4*)(g_gru + (size_t)bt * Hh))[tid];
    float4 b = ((const float4*)(g_M2 + (size_t)k * Hh))[tid];
    float s = a.x*b.x + a.y*b.y + a.z*b.z + a.w*b.w;
#pragma unroll
    for (int o = 16; o > 0; o >>= 1) s += __shfl_down_sync(0xffffffffu, s, o);
    __shared__ float red[4];
    if ((tid & 31) == 0) red[tid >> 5] = s;
    __syncthreads();
    if (tid == 0) {
        float got = red[0] + red[1] + red[2] + red[3] + g_cvec[k];
        g_mvals[bt] = (got >= 0.4f) ? 1.0f : got;
    }
}

__global__ __launch_bounds__(256) void dina_kernel(const int* __restrict__ qd,
                                                   const int* __restrict__ qad,
                                                   const float* __restrict__ target,
                                                   float* __restrict__ out, int out_size) {
    __shared__ int qs[Lsz];
    __shared__ float qaS[Lsz], mvS[Lsz], mcS[Lsz], miS[Lsz], nmcS[Lsz], aaS[Lsz];
    __shared__ float guess[Qq], slip[Qq];
    int b = blockIdx.x, tid = threadIdx.x;
    const int off = (out_size >= BL + 2) ? 1 : 0;   // defensive output layout
    for (int i = tid; i < Qq; i += 256) { guess[i] = 0.f; slip[i] = 0.f; }
    if (tid < Lsz) {
        int bt = b * Lsz + tid;
        int q = qd[bt];
        qs[tid] = q;
        qaS[tid] = (float)((qad[bt] - q) / NQc);
        mvS[tid] = g_mvals[bt];
    }
    __syncthreads();
    if (tid < Lsz) {
        int qt = qs[tid];
        float mc = 0.f, mi = 0.f, nmc = 0.f, aa = 0.f;
        for (int k = 0; k <= tid; ++k) {
            if (qs[k] == qt) {
                aa += 1.f;
                if (k < tid) {
                    float qa1 = qaS[k];
                    float ma = (mvS[k] == 1.f) ? 1.f : 0.f;
                    float nm = (mvS[k] == 0.f) ? 1.f : 0.f;
                    mc += qa1 * ma; mi += (1.f - qa1) * ma; nmc += (1.f - qa1) * nm;
                }
            }
        }
        mcS[tid] = mc; miS[tid] = mi; nmcS[tid] = nmc; aaS[tid] = aa;
    }
    __syncthreads();
    if (tid == 0) {
        float mse = 0.f, cnt = 0.f;
        for (int t = 0; t < Lsz; ++t) {
            int i = qs[t] - 1;
            float m = mvS[t], qa = qaS[t], aa = aaS[t];
            float g_upd = (m == 1.f) ? mcS[t] / aa
                        : ((qa == 0.f) ? 1.f - nmcS[t] / aa : nmcS[t] / aa);
            bool us = (m == 1.f) && (qa == 0.f);
            float ng = us ? guess[i] : g_upd;
            float ns = us ? miS[t] / aa : slip[i];
            guess[i] = ng; slip[i] = ns;
            float p = (1.f - ns) * (m * ng + (1.f - ns) * (1.f - m));
            float lab = target[b * Lsz + t];
            if (lab > -0.9f) { float d = p - lab; mse += d * d; cnt += 1.f; }
            out[off + b * Lsz + t] = 1.f / (1.f + expf(-p));
        }
        atomicAdd(&g_mse, mse);
        atomicAdd(&g_cnt, cnt);
    }
}

__global__ void finalize_kernel(float* __restrict__ out, int out_size) {
    if (threadIdx.x == 0 && out_size >= BL + 2) {
        out[0] = g_mse + 1e-5f * g_creg;
        out[BL + 1] = g_cnt;
    }
}

extern "C" void kernel_launch(void* const* d_in, const int* in_sizes, int n_in,
                              void* d_out, int out_size) {
    const int*   qd     = (const int*)d_in[0];
    const int*   qad    = (const int*)d_in[1];
    const int*   pidd   = (const int*)d_in[2];
    const float* matrix = (const float*)d_in[3];
    const float* target = (const float*)d_in[4];
    const float* q_emb  = (const float*)d_in[5];
    const float* qa_emb = (const float*)d_in[6];
    const float* q_ed   = (const float*)d_in[7];
    const float* qa_ed  = (const float*)d_in[8];
    const float* dparm  = (const float*)d_in[9];
    const float* w_ih   = (const float*)d_in[10];
    const float* w_hh   = (const float*)d_in[11];
    const float* b_ih   = (const float*)d_in[12];
    const float* b_hh   = (const float*)d_in[13];
    const float* fc_w   = (const float*)d_in[14];
    const float* fc_b   = (const float*)d_in[15];
    float* out = (float*)d_out;

    cudaFuncSetAttribute(gru_kernel, cudaFuncAttributeMaxDynamicSharedMemorySize,
                         (int)GRU_SMEM);

    init_kernel<<<128, 256>>>();
    embed_kernel<<<BL, 128>>>(qd, qad, pidd, q_emb, qa_emb, q_ed, qa_ed, dparm);
    sgemm128_bt<<<dim3(H3 / 128, BL / 128), 256>>>(w_ih, b_ih);
    sgemm64_nn<<<dim3(Hh / 64, Qq / 64), 256>>>(matrix, fc_w);
    cvec_kernel<<<Qq, 256>>>(matrix, fc_b);
    gru_kernel<<<128, 256, GRU_SMEM>>>(w_hh, b_hh);
    master_kernel<<<BL, 128>>>(qd);
    dina_kernel<<<Bsz, 256>>>(qd, qad, target, out, out_size);
    finalize_kernel<<<1, 32>>>(out, out_size);
}

// round 9
// speedup vs baseline: 1.3755x; 1.3755x over previous
#include <cuda_runtime.h>
#include <math.h>

#define Bsz 64
#define Lsz 200
#define BL  12800
#define Dd  256
#define Hh  512
#define H3  1536
#define Qq  1024
#define NQc 1024
#define NQ1 1025
#define WS_STRIDE 516
#define GRU_SMEM ((48*WS_STRIDE + 16*WS_STRIDE + 48*16*4) * sizeof(float))

typedef unsigned long long u64;
union F2U { u64 u; float2 f; };

__device__ __forceinline__ u64 ffma2(u64 a, u64 b, u64 c) {
    u64 d;
    asm("fma.rn.f32x2 %0, %1, %2, %3;" : "=l"(d) : "l"(a), "l"(b), "l"(c));
    return d;
}
__device__ __forceinline__ u64 splat2(float x) {
    u64 d;
    asm("mov.b64 %0, {%1, %1};" : "=l"(d) : "f"(x));
    return d;
}

__device__ __align__(16) float g_xg[(size_t)BL * H3];
__device__ __align__(16) float g_gru[(size_t)BL * Hh];
__device__ __align__(16) float g_h[2][Bsz * Hh];
__device__ __align__(16) float g_M2[(size_t)Qq * Hh];
__device__ __align__(16) float g_P[(size_t)NQ1 * H3];
__device__ __align__(16) float g_R[(size_t)NQ1 * H3];
__device__ __align__(16) float g_c[2 * H3];
__device__ __align__(16) float g_d[2 * H3];
__device__ float g_cvec[Qq];
__device__ float g_mvals[BL];
__device__ float g_mse, g_creg, g_cnt;
__device__ unsigned g_bar_count;
__device__ volatile unsigned g_bar_gen;

__global__ void init_kernel() {
    int idx = blockIdx.x * 256 + threadIdx.x;
    if (idx < Bsz * Hh) g_h[0][idx] = 0.0f;
    if (idx == 0) { g_mse = 0.f; g_creg = 0.f; g_cnt = 0.f; g_bar_count = 0u; g_bar_gen = 0u; }
}

// out[1025,1536] = E[1025,256] @ Wslice[1536,256]^T
// mode 0: Wslice = W1+W2 (cols 0:256 + cols 256:512 of w_ih)
// mode 1: Wslice = W2 (cols 256:512)
__global__ __launch_bounds__(256, 2) void sgemm_embed(const float* __restrict__ E,
                                                      const float* __restrict__ wih,
                                                      float* __restrict__ outp, int mode) {
    const int N = H3, K = Dd, M = NQ1;
    __shared__ float As[16 * 128];
    __shared__ float Bs[16 * 128];
    const int m0 = blockIdx.y * 128, n0 = blockIdx.x * 128;
    const int tid = threadIdx.x, tx = tid & 15, ty = tid >> 4;
    u64 acc2[8][4];
#pragma unroll
    for (int i = 0; i < 8; ++i)
#pragma unroll
        for (int j = 0; j < 4; ++j) acc2[i][j] = 0ull;
    for (int kt = 0; kt < K; kt += 16) {
#pragma unroll
        for (int jj = 0; jj < 2; ++jj) {
            int idx = tid + jj * 256;
            int m = idx & 127, kq = idx >> 7;
            int am = m0 + m; if (am >= M) am = M - 1;
            float4 va = *(const float4*)&E[(size_t)am * K + kt + kq * 4];
            As[(kq*4+0)*128 + m] = va.x; As[(kq*4+1)*128 + m] = va.y;
            As[(kq*4+2)*128 + m] = va.z; As[(kq*4+3)*128 + m] = va.w;
            const float* wrow = &wih[(size_t)(n0 + m) * 512 + kt + kq * 4];
            float4 vb = *(const float4*)&wrow[256];
            if (mode == 0) {
                float4 v1 = *(const float4*)&wrow[0];
                vb.x += v1.x; vb.y += v1.y; vb.z += v1.z; vb.w += v1.w;
            }
            Bs[(kq*4+0)*128 + m] = vb.x; Bs[(kq*4+1)*128 + m] = vb.y;
            Bs[(kq*4+2)*128 + m] = vb.z; Bs[(kq*4+3)*128 + m] = vb.w;
        }
        __syncthreads();
#pragma unroll
        for (int k = 0; k < 16; ++k) {
            float4 a0 = *(float4*)&As[k*128 + ty*8];
            float4 a1 = *(float4*)&As[k*128 + ty*8 + 4];
            ulonglong2 bq0 = *(ulonglong2*)&Bs[k*128 + tx*8];
            ulonglong2 bq1 = *(ulonglong2*)&Bs[k*128 + tx*8 + 4];
            u64 b2[4] = {bq0.x, bq0.y, bq1.x, bq1.y};
            float av[8] = {a0.x,a0.y,a0.z,a0.w,a1.x,a1.y,a1.z,a1.w};
            u64 a2[8];
#pragma unroll
            for (int i = 0; i < 8; ++i) a2[i] = splat2(av[i]);
#pragma unroll
            for (int i = 0; i < 8; ++i)
#pragma unroll
                for (int j = 0; j < 4; ++j) acc2[i][j] = ffma2(a2[i], b2[j], acc2[i][j]);
        }
        __syncthreads();
    }
#pragma unroll
    for (int i = 0; i < 8; ++i) {
        int row = m0 + ty*8 + i;
        if (row < M) {
            size_t o = (size_t)row * N + n0 + tx*8;
            float v[8];
#pragma unroll
            for (int j = 0; j < 4; ++j) {
                F2U u; u.u = acc2[i][j];
                v[2*j] = u.f.x; v[2*j+1] = u.f.y;
            }
            *(float4*)&outp[o]     = make_float4(v[0], v[1], v[2], v[3]);
            *(float4*)&outp[o + 4] = make_float4(v[4], v[5], v[6], v[7]);
        }
    }
}

// c[qa][n] = qa_emb[qa] . W1[n,:],  d[qa][n] = qa_ed[qa] . W1[n,:]
__global__ void cd_kernel(const float* __restrict__ qa_emb, const float* __restrict__ qa_ed,
                          const float* __restrict__ wih) {
    __shared__ float e[4][Dd];
    int tid = threadIdx.x;
    for (int i = tid; i < 4 * Dd; i += 256) {
        int r = i >> 8, k = i & 255;
        e[r][k] = (r < 2) ? qa_emb[r * Dd + k] : qa_ed[(r - 2) * Dd + k];
    }
    __syncthreads();
    int n = blockIdx.x * 256 + tid;
    const float* w = &wih[(size_t)n * 512];
    float a0 = 0.f, a1 = 0.f, a2 = 0.f, a3 = 0.f;
#pragma unroll 8
    for (int k = 0; k < Dd; ++k) {
        float wv = w[k];
        a0 += wv * e[0][k]; a1 += wv * e[1][k];
        a2 += wv * e[2][k]; a3 += wv * e[3][k];
    }
    g_c[n] = a0; g_c[H3 + n] = a1;
    g_d[n] = a2; g_d[H3 + n] = a3;
}

// xg[bt] = P[q] + c[qa] + pid*(d[qa] + R[q]) + b_ih
__global__ __launch_bounds__(384) void xg_build(const int* __restrict__ qd,
                                                const int* __restrict__ qad,
                                                const int* __restrict__ pidd,
                                                const float* __restrict__ dparm,
                                                const float* __restrict__ b_ih) {
    int bt = blockIdx.x;
    int q = qd[bt];
    int qa = (qad[bt] - q) / NQc;
    float pid = dparm[pidd[bt]];
    int tid = threadIdx.x;
    if (tid == 0) atomicAdd(&g_creg, pid * pid);
    float4 P = ((const float4*)&g_P[(size_t)q * H3])[tid];
    float4 R = ((const float4*)&g_R[(size_t)q * H3])[tid];
    float4 c = ((const float4*)&g_c[qa * H3])[tid];
    float4 d = ((const float4*)&g_d[qa * H3])[tid];
    float4 bb = ((const float4*)b_ih)[tid];
    float4 r;
    r.x = P.x + c.x + pid * (d.x + R.x) + bb.x;
    r.y = P.y + c.y + pid * (d.y + R.y) + bb.y;
    r.z = P.z + c.z + pid * (d.z + R.z) + bb.z;
    r.w = P.w + c.w + pid * (d.w + R.w) + bb.w;
    ((float4*)&g_xg[(size_t)bt * H3])[tid] = r;
}

// g_M2[1024,512] = matrix[1024,1024] @ fc_w[1024,512]
__global__ __launch_bounds__(256, 4) void sgemm64_nn(const float* __restrict__ A,
                                                     const float* __restrict__ B) {
    const int N = Hh, K = Qq;
    __shared__ float As[16 * 64];
    __shared__ float Bs[16 * 64];
    const int m0 = blockIdx.y * 64, n0 = blockIdx.x * 64;
    const int tid = threadIdx.x, tx = tid & 15, ty = tid >> 4;
    float acc[4][4];
#pragma unroll
    for (int i = 0; i < 4; ++i)
#pragma unroll
        for (int j = 0; j < 4; ++j) acc[i][j] = 0.0f;
    for (int kt = 0; kt < K; kt += 16) {
        int m = tid & 63, kq = tid >> 6;
        float4 va = *(const float4*)&A[(size_t)(m0 + m) * K + kt + kq * 4];
        As[(kq*4+0)*64 + m] = va.x; As[(kq*4+1)*64 + m] = va.y;
        As[(kq*4+2)*64 + m] = va.z; As[(kq*4+3)*64 + m] = va.w;
        int kk = tid >> 4, nq = tid & 15;
        *(float4*)&Bs[kk*64 + nq*4] = *(const float4*)&B[(size_t)(kt + kk) * N + n0 + nq * 4];
        __syncthreads();
#pragma unroll
        for (int k = 0; k < 16; ++k) {
            float4 a = *(float4*)&As[k*64 + ty*4];
            float4 b = *(float4*)&Bs[k*64 + tx*4];
            float av[4] = {a.x,a.y,a.z,a.w};
            float bv[4] = {b.x,b.y,b.z,b.w};
#pragma unroll
            for (int i = 0; i < 4; ++i)
#pragma unroll
                for (int j = 0; j < 4; ++j) acc[i][j] += av[i] * bv[j];
        }
        __syncthreads();
    }
#pragma unroll
    for (int i = 0; i < 4; ++i) {
        float4 o; o.x = acc[i][0]; o.y = acc[i][1]; o.z = acc[i][2]; o.w = acc[i][3];
        *(float4*)&g_M2[(size_t)(m0 + ty*4 + i) * N + n0 + tx*4] = o;
    }
}

__global__ void cvec_kernel(const float* __restrict__ matrix, const float* __restrict__ fc_b) {
    int row = blockIdx.x, tid = threadIdx.x;
    float4 a = ((const float4*)(matrix + (size_t)row * Qq))[tid];
    float4 b = ((const float4*)fc_b)[tid];
    float s = a.x*b.x + a.y*b.y + a.z*b.z + a.w*b.w;
#pragma unroll
    for (int o = 16; o > 0; o >>= 1) s += __shfl_down_sync(0xffffffffu, s, o);
    __shared__ float red[8];
    if ((tid & 31) == 0) red[tid >> 5] = s;
    __syncthreads();
    if (tid == 0) {
        float t = 0.f;
#pragma unroll
        for (int w = 0; w < 8; ++w) t += red[w];
        g_cvec[row] = t;
    }
}

// Persistent GRU: 128 blocks x 256 thr, block = 16b x 16j, w slice in smem.
__global__ __launch_bounds__(256, 1) void gru_kernel(const float* __restrict__ w_hh,
                                                     const float* __restrict__ b_hh) {
    extern __shared__ float sm[];
    float* ws = sm;
    float* hs = ws + 48 * WS_STRIDE;
    float* ps = hs + 16 * WS_STRIDE;
    const int tid = threadIdx.x;
    const int bg = blockIdx.x & 3, jg = blockIdx.x >> 2;
    const int b0 = bg * 16, j0 = jg * 16;
    for (int i = tid; i < 48 * 128; i += 256) {
        int row = i >> 7, k4 = (i & 127) * 4;
        int jj = row / 3, g = row % 3;
        *(float4*)&ws[row * WS_STRIDE + k4] =
            *(const float4*)&w_hh[((size_t)(g * Hh + j0 + jj)) * Hh + k4];
    }
    const int tb = tid & 3, tjg = (tid >> 2) & 15, ks = tid >> 6;
    const int cbb = tid & 15, cjj = tid >> 4;
    const int cb = b0 + cbb, cj = j0 + cjj;
    const float bh0 = b_hh[0 * Hh + cj];
    const float bh1 = b_hh[1 * Hh + cj];
    const float bh2 = b_hh[2 * Hh + cj];
    for (int t = 0; t < Lsz; ++t) {
        // Prefetch gate inputs early (h-independent; hides L2 latency)
        const float* xgp = &g_xg[((size_t)cb * Lsz + t) * H3];
        float xr = __ldg(&xgp[cj]);
        float xz = __ldg(&xgp[Hh + cj]);
        float xn = __ldg(&xgp[2 * Hh + cj]);
        const float* hsrc = g_h[t & 1];
        for (int i = tid; i < 16 * 128; i += 256) {
            int bb = i >> 7, k4 = (i & 127) * 4;
            float4 v = __ldcg((const float4*)&hsrc[(b0 + bb) * Hh + k4]);
            *(float4*)&hs[bb * WS_STRIDE + k4] = v;
        }
        __syncthreads();
        u64 acc2[3][4];
#pragma unroll
        for (int g = 0; g < 3; ++g)
#pragma unroll
            for (int i = 0; i < 4; ++i) acc2[g][i] = 0ull;
        const int kb = ks * 128;
#pragma unroll 4
        for (int k = kb; k < kb + 128; k += 4) {
            ulonglong2 h2[4];
#pragma unroll
            for (int i = 0; i < 4; ++i)
                h2[i] = *(ulonglong2*)&hs[(i*4 + tb) * WS_STRIDE + k];
#pragma unroll
            for (int g = 0; g < 3; ++g) {
                ulonglong2 w2 = *(ulonglong2*)&ws[(tjg*3 + g) * WS_STRIDE + k];
#pragma unroll
                for (int i = 0; i < 4; ++i) {
                    acc2[g][i] = ffma2(h2[i].x, w2.x, acc2[g][i]);
                    acc2[g][i] = ffma2(h2[i].y, w2.y, acc2[g][i]);
                }
            }
        }
#pragma unroll
        for (int g = 0; g < 3; ++g)
#pragma unroll
            for (int i = 0; i < 4; ++i) {
                F2U v; v.u = acc2[g][i];
                ps[((tjg*3 + g) * 16 + (i*4 + tb)) * 4 + ks] = v.f.x + v.f.y;
            }
        __syncthreads();
        {
            const float* pp0 = &ps[((cjj*3 + 0) * 16 + cbb) * 4];
            const float* pp1 = &ps[((cjj*3 + 1) * 16 + cbb) * 4];
            const float* pp2 = &ps[((cjj*3 + 2) * 16 + cbb) * 4];
            float hg0 = pp0[0] + pp0[1] + pp0[2] + pp0[3] + bh0;
            float hg1 = pp1[0] + pp1[1] + pp1[2] + pp1[3] + bh1;
            float hg2 = pp2[0] + pp2[1] + pp2[2] + pp2[3] + bh2;
            float r = 1.0f / (1.0f + expf(-(xr + hg0)));
            float z = 1.0f / (1.0f + expf(-(xz + hg1)));
            float n = tanhf(xn + r * hg2);
            float hprev = hs[cbb * WS_STRIDE + cj];
            float hnew = (1.0f - z) * n + z * hprev;
            g_h[(t + 1) & 1][cb * Hh + cj] = hnew;
            g_gru[((size_t)cb * Lsz + t) * Hh + cj] = hnew;
        }
        __syncthreads();
        if (tid == 0) {
            __threadfence();
            unsigned gen = g_bar_gen;
            if (atomicAdd(&g_bar_count, 1u) == 127u) {
                g_bar_count = 0u;
                __threadfence();
                g_bar_gen = gen + 1u;
            } else {
                while (g_bar_gen == gen) {}
                __threadfence();
            }
        }
        __syncthreads();
    }
}

__global__ void master_kernel(const int* __restrict__ qd) {
    int bt = blockIdx.x, tid = threadIdx.x;
    int k = qd[bt] - 1;
    float4 a = ((const float4*)(g_gru + (size_t)bt * Hh))[tid];
    float4 b = ((const float4*)(g_M2 + (size_t)k * Hh))[tid];
    float s = a.x*b.x + a.y*b.y + a.z*b.z + a.w*b.w;
#pragma unroll
    for (int o = 16; o > 0; o >>= 1) s += __shfl_down_sync(0xffffffffu, s, o);
    __shared__ float red[4];
    if ((tid & 31) == 0) red[tid >> 5] = s;
    __syncthreads();
    if (tid == 0) {
        float got = red[0] + red[1] + red[2] + red[3] + g_cvec[k];
        g_mvals[bt] = (got >= 0.4f) ? 1.0f : got;
    }
}

__global__ __launch_bounds__(256) void dina_kernel(const int* __restrict__ qd,
                                                   const int* __restrict__ qad,
                                                   const float* __restrict__ target,
                                                   float* __restrict__ out, int out_size) {
    __shared__ int qs[Lsz];
    __shared__ float qaS[Lsz], mvS[Lsz], mcS[Lsz], miS[Lsz], nmcS[Lsz], aaS[Lsz];
    __shared__ float guess[Qq], slip[Qq];
    int b = blockIdx.x, tid = threadIdx.x;
    const int off = (out_size >= BL + 2) ? 1 : 0;
    for (int i = tid; i < Qq; i += 256) { guess[i] = 0.f; slip[i] = 0.f; }
    if (tid < Lsz) {
        int bt = b * Lsz + tid;
        int q = qd[bt];
        qs[tid] = q;
        qaS[tid] = (float)((qad[bt] - q) / NQc);
        mvS[tid] = g_mvals[bt];
    }
    __syncthreads();
    if (tid < Lsz) {
        int qt = qs[tid];
        float mc = 0.f, mi = 0.f, nmc = 0.f, aa = 0.f;
        for (int k = 0; k <= tid; ++k) {
            if (qs[k] == qt) {
                aa += 1.f;
                if (k < tid) {
                    float qa1 = qaS[k];
                    float ma = (mvS[k] == 1.f) ? 1.f : 0.f;
                    float nm = (mvS[k] == 0.f) ? 1.f : 0.f;
                    mc += qa1 * ma; mi += (1.f - qa1) * ma; nmc += (1.f - qa1) * nm;
                }
            }
        }
        mcS[tid] = mc; miS[tid] = mi; nmcS[tid] = nmc; aaS[tid] = aa;
    }
    __syncthreads();
    if (tid == 0) {
        float mse = 0.f, cnt = 0.f;
        for (int t = 0; t < Lsz; ++t) {
            int i = qs[t] - 1;
            float m = mvS[t], qa = qaS[t], aa = aaS[t];
            float g_upd = (m == 1.f) ? mcS[t] / aa
                        : ((qa == 0.f) ? 1.f - nmcS[t] / aa : nmcS[t] / aa);
            bool us = (m == 1.f) && (qa == 0.f);
            float ng = us ? guess[i] : g_upd;
            float ns = us ? miS[t] / aa : slip[i];
            guess[i] = ng; slip[i] = ns;
            float p = (1.f - ns) * (m * ng + (1.f - ns) * (1.f - m));
            float lab = target[b * Lsz + t];
            if (lab > -0.9f) { float d = p - lab; mse += d * d; cnt += 1.f; }
            out[off + b * Lsz + t] = 1.f / (1.f + expf(-p));
        }
        atomicAdd(&g_mse, mse);
        atomicAdd(&g_cnt, cnt);
    }
}

__global__ void finalize_kernel(float* __restrict__ out, int out_size) {
    if (threadIdx.x == 0 && out_size >= BL + 2) {
        out[0] = g_mse + 1e-5f * g_creg;
        out[BL + 1] = g_cnt;
    }
}

extern "C" void kernel_launch(void* const* d_in, const int* in_sizes, int n_in,
                              void* d_out, int out_size) {
    const int*   qd     = (const int*)d_in[0];
    const int*   qad    = (const int*)d_in[1];
    const int*   pidd   = (const int*)d_in[2];
    const float* matrix = (const float*)d_in[3];
    const float* target = (const float*)d_in[4];
    const float* q_emb  = (const float*)d_in[5];
    const float* qa_emb = (const float*)d_in[6];
    const float* q_ed   = (const float*)d_in[7];
    const float* qa_ed  = (const float*)d_in[8];
    const float* dparm  = (const float*)d_in[9];
    const float* w_ih   = (const float*)d_in[10];
    const float* w_hh   = (const float*)d_in[11];
    const float* b_ih   = (const float*)d_in[12];
    const float* b_hh   = (const float*)d_in[13];
    const float* fc_w   = (const float*)d_in[14];
    const float* fc_b   = (const float*)d_in[15];
    float* out = (float*)d_out;

    float* dev_P = nullptr; float* dev_R = nullptr;
    cudaGetSymbolAddress((void**)&dev_P, g_P);
    cudaGetSymbolAddress((void**)&dev_R, g_R);

    cudaFuncSetAttribute(gru_kernel, cudaFuncAttributeMaxDynamicSharedMemorySize,
                         (int)GRU_SMEM);

    init_kernel<<<128, 256>>>();
    sgemm_embed<<<dim3(H3 / 128, (NQ1 + 127) / 128), 256>>>(q_emb, w_ih, dev_P, 0);
    sgemm_embed<<<dim3(H3 / 128, (NQ1 + 127) / 128), 256>>>(q_ed, w_ih, dev_R, 1);
    cd_kernel<<<H3 / 256, 256>>>(qa_emb, qa_ed, w_ih);
    xg_build<<<BL, 384>>>(qd, qad, pidd, dparm, b_ih);
    sgemm64_nn<<<dim3(Hh / 64, Qq / 64), 256>>>(matrix, fc_w);
    cvec_kernel<<<Qq, 256>>>(matrix, fc_b);
    gru_kernel<<<128, 256, GRU_SMEM>>>(w_hh, b_hh);
    master_kernel<<<BL, 128>>>(qd);
    dina_kernel<<<Bsz, 256>>>(qd, qad, target, out, out_size);
    finalize_kernel<<<1, 32>>>(out, out_size);
}

// round 11
// speedup vs baseline: 1.5870x; 1.1537x over previous
#include <cuda_runtime.h>
#include <math.h>

#define Bsz 64
#define Lsz 200
#define BL  12800
#define Dd  256
#define Hh  512
#define H3  1536
#define Qq  1024
#define NQc 1024
#define NQ1 1025
#define WS_STRIDE 516
#define GRU_SMEM ((48*WS_STRIDE + 16*WS_STRIDE + 48*16*4) * sizeof(float))

typedef unsigned long long u64;
union F2U { u64 u; float2 f; };

__device__ __forceinline__ u64 ffma2(u64 a, u64 b, u64 c) {
    u64 d;
    asm("fma.rn.f32x2 %0, %1, %2, %3;" : "=l"(d) : "l"(a), "l"(b), "l"(c));
    return d;
}
__device__ __forceinline__ u64 splat2(float x) {
    u64 d;
    asm("mov.b64 %0, {%1, %1};" : "=l"(d) : "f"(x));
    return d;
}

__device__ __align__(16) float g_xg[(size_t)BL * H3];
__device__ __align__(16) float g_gru[(size_t)BL * Hh];
__device__ __align__(16) float g_h[2][Bsz * Hh];
__device__ __align__(16) float g_M2[(size_t)Qq * Hh];
__device__ __align__(16) float g_P[(size_t)NQ1 * H3];
__device__ __align__(16) float g_R[(size_t)NQ1 * H3];
__device__ __align__(16) float g_c[2 * H3];
__device__ __align__(16) float g_d[2 * H3];
__device__ float g_cvec[Qq];
__device__ float g_mvals[BL];
__device__ float g_mse, g_creg, g_cnt;
__device__ unsigned g_flags[128];   // per-(bg,jg) step counters; 4 groups of 32

__global__ void init_kernel() {
    int idx = blockIdx.x * 256 + threadIdx.x;
    if (idx < Bsz * Hh) g_h[0][idx] = 0.0f;
    if (idx < 128) g_flags[idx] = 0u;
    if (idx == 0) { g_mse = 0.f; g_creg = 0.f; g_cnt = 0.f; }
}

// out[1025,1536] = E[1025,256] @ Wslice[1536,256]^T
// mode 0: Wslice = W1+W2 (cols 0:256 + 256:512 of w_ih); mode 1: W2 only
__global__ __launch_bounds__(256, 2) void sgemm_embed(const float* __restrict__ E,
                                                      const float* __restrict__ wih,
                                                      float* __restrict__ outp, int mode) {
    const int N = H3, K = Dd, M = NQ1;
    __shared__ float As[16 * 128];
    __shared__ float Bs[16 * 128];
    const int m0 = blockIdx.y * 128, n0 = blockIdx.x * 128;
    const int tid = threadIdx.x, tx = tid & 15, ty = tid >> 4;
    u64 acc2[8][4];
#pragma unroll
    for (int i = 0; i < 8; ++i)
#pragma unroll
        for (int j = 0; j < 4; ++j) acc2[i][j] = 0ull;
    for (int kt = 0; kt < K; kt += 16) {
#pragma unroll
        for (int jj = 0; jj < 2; ++jj) {
            int idx = tid + jj * 256;
            int m = idx & 127, kq = idx >> 7;
            int am = m0 + m; if (am >= M) am = M - 1;
            float4 va = *(const float4*)&E[(size_t)am * K + kt + kq * 4];
            As[(kq*4+0)*128 + m] = va.x; As[(kq*4+1)*128 + m] = va.y;
            As[(kq*4+2)*128 + m] = va.z; As[(kq*4+3)*128 + m] = va.w;
            const float* wrow = &wih[(size_t)(n0 + m) * 512 + kt + kq * 4];
            float4 vb = *(const float4*)&wrow[256];
            if (mode == 0) {
                float4 v1 = *(const float4*)&wrow[0];
                vb.x += v1.x; vb.y += v1.y; vb.z += v1.z; vb.w += v1.w;
            }
            Bs[(kq*4+0)*128 + m] = vb.x; Bs[(kq*4+1)*128 + m] = vb.y;
            Bs[(kq*4+2)*128 + m] = vb.z; Bs[(kq*4+3)*128 + m] = vb.w;
        }
        __syncthreads();
#pragma unroll
        for (int k = 0; k < 16; ++k) {
            float4 a0 = *(float4*)&As[k*128 + ty*8];
            float4 a1 = *(float4*)&As[k*128 + ty*8 + 4];
            ulonglong2 bq0 = *(ulonglong2*)&Bs[k*128 + tx*8];
            ulonglong2 bq1 = *(ulonglong2*)&Bs[k*128 + tx*8 + 4];
            u64 b2[4] = {bq0.x, bq0.y, bq1.x, bq1.y};
            float av[8] = {a0.x,a0.y,a0.z,a0.w,a1.x,a1.y,a1.z,a1.w};
            u64 a2[8];
#pragma unroll
            for (int i = 0; i < 8; ++i) a2[i] = splat2(av[i]);
#pragma unroll
            for (int i = 0; i < 8; ++i)
#pragma unroll
                for (int j = 0; j < 4; ++j) acc2[i][j] = ffma2(a2[i], b2[j], acc2[i][j]);
        }
        __syncthreads();
    }
#pragma unroll
    for (int i = 0; i < 8; ++i) {
        int row = m0 + ty*8 + i;
        if (row < M) {
            size_t o = (size_t)row * N + n0 + tx*8;
            float v[8];
#pragma unroll
            for (int j = 0; j < 4; ++j) {
                F2U u; u.u = acc2[i][j];
                v[2*j] = u.f.x; v[2*j+1] = u.f.y;
            }
            *(float4*)&outp[o]     = make_float4(v[0], v[1], v[2], v[3]);
            *(float4*)&outp[o + 4] = make_float4(v[4], v[5], v[6], v[7]);
        }
    }
}

// warp-per-output: c[qa][n] = qa_emb[qa].W1[n,:], d[qa][n] = qa_ed[qa].W1[n,:]
__global__ __launch_bounds__(256) void cd_kernel(const float* __restrict__ qa_emb,
                                                 const float* __restrict__ qa_ed,
                                                 const float* __restrict__ wih) {
    __shared__ float e[4][Dd];
    int tid = threadIdx.x;
    for (int i = tid; i < 4 * Dd; i += 256) {
        int r = i >> 8, k = i & 255;
        e[r][k] = (r < 2) ? qa_emb[r * Dd + k] : qa_ed[(r - 2) * Dd + k];
    }
    __syncthreads();
    int n = blockIdx.x * 8 + (tid >> 5);   // warp id -> output row
    int lane = tid & 31;
    const float* w = &wih[(size_t)n * 512];
    float a0 = 0.f, a1 = 0.f, a2 = 0.f, a3 = 0.f;
#pragma unroll
    for (int k = lane; k < Dd; k += 32) {
        float wv = w[k];
        a0 += wv * e[0][k]; a1 += wv * e[1][k];
        a2 += wv * e[2][k]; a3 += wv * e[3][k];
    }
#pragma unroll
    for (int o = 16; o > 0; o >>= 1) {
        a0 += __shfl_down_sync(0xffffffffu, a0, o);
        a1 += __shfl_down_sync(0xffffffffu, a1, o);
        a2 += __shfl_down_sync(0xffffffffu, a2, o);
        a3 += __shfl_down_sync(0xffffffffu, a3, o);
    }
    if (lane == 0) {
        g_c[n] = a0; g_c[H3 + n] = a1;
        g_d[n] = a2; g_d[H3 + n] = a3;
    }
}

// xg[bt] = P[q] + c[qa] + pid*(d[qa] + R[q]) + b_ih
__global__ __launch_bounds__(384) void xg_build(const int* __restrict__ qd,
                                                const int* __restrict__ qad,
                                                const int* __restrict__ pidd,
                                                const float* __restrict__ dparm,
                                                const float* __restrict__ b_ih) {
    int bt = blockIdx.x;
    int q = qd[bt];
    int qa = (qad[bt] - q) / NQc;
    float pid = dparm[pidd[bt]];
    int tid = threadIdx.x;
    if (tid == 0) atomicAdd(&g_creg, pid * pid);
    float4 P = ((const float4*)&g_P[(size_t)q * H3])[tid];
    float4 R = ((const float4*)&g_R[(size_t)q * H3])[tid];
    float4 c = ((const float4*)&g_c[qa * H3])[tid];
    float4 d = ((const float4*)&g_d[qa * H3])[tid];
    float4 bb = ((const float4*)b_ih)[tid];
    float4 r;
    r.x = P.x + c.x + pid * (d.x + R.x) + bb.x;
    r.y = P.y + c.y + pid * (d.y + R.y) + bb.y;
    r.z = P.z + c.z + pid * (d.z + R.z) + bb.z;
    r.w = P.w + c.w + pid * (d.w + R.w) + bb.w;
    ((float4*)&g_xg[(size_t)bt * H3])[tid] = r;
}

// g_M2[1024,512] = matrix[1024,1024] @ fc_w[1024,512]
__global__ __launch_bounds__(256, 4) void sgemm64_nn(const float* __restrict__ A,
                                                     const float* __restrict__ B) {
    const int N = Hh, K = Qq;
    __shared__ float As[16 * 64];
    __shared__ float Bs[16 * 64];
    const int m0 = blockIdx.y * 64, n0 = blockIdx.x * 64;
    const int tid = threadIdx.x, tx = tid & 15, ty = tid >> 4;
    float acc[4][4];
#pragma unroll
    for (int i = 0; i < 4; ++i)
#pragma unroll
        for (int j = 0; j < 4; ++j) acc[i][j] = 0.0f;
    for (int kt = 0; kt < K; kt += 16) {
        int m = tid & 63, kq = tid >> 6;
        float4 va = *(const float4*)&A[(size_t)(m0 + m) * K + kt + kq * 4];
        As[(kq*4+0)*64 + m] = va.x; As[(kq*4+1)*64 + m] = va.y;
        As[(kq*4+2)*64 + m] = va.z; As[(kq*4+3)*64 + m] = va.w;
        int kk = tid >> 4, nq = tid & 15;
        *(float4*)&Bs[kk*64 + nq*4] = *(const float4*)&B[(size_t)(kt + kk) * N + n0 + nq * 4];
        __syncthreads();
#pragma unroll
        for (int k = 0; k < 16; ++k) {
            float4 a = *(float4*)&As[k*64 + ty*4];
            float4 b = *(float4*)&Bs[k*64 + tx*4];
            float av[4] = {a.x,a.y,a.z,a.w};
            float bv[4] = {b.x,b.y,b.z,b.w};
#pragma unroll
            for (int i = 0; i < 4; ++i)
#pragma unroll
                for (int j = 0; j < 4; ++j) acc[i][j] += av[i] * bv[j];
        }
        __syncthreads();
    }
#pragma unroll
    for (int i = 0; i < 4; ++i) {
        float4 o; o.x = acc[i][0]; o.y = acc[i][1]; o.z = acc[i][2]; o.w = acc[i][3];
        *(float4*)&g_M2[(size_t)(m0 + ty*4 + i) * N + n0 + tx*4] = o;
    }
}

__global__ void cvec_kernel(const float* __restrict__ matrix, const float* __restrict__ fc_b) {
    int row = blockIdx.x, tid = threadIdx.x;
    float4 a = ((const float4*)(matrix + (size_t)row * Qq))[tid];
    float4 b = ((const float4*)fc_b)[tid];
    float s = a.x*b.x + a.y*b.y + a.z*b.z + a.w*b.w;
#pragma unroll
    for (int o = 16; o > 0; o >>= 1) s += __shfl_down_sync(0xffffffffu, s, o);
    __shared__ float red[8];
    if ((tid & 31) == 0) red[tid >> 5] = s;
    __syncthreads();
    if (tid == 0) {
        float t = 0.f;
#pragma unroll
        for (int w = 0; w < 8; ++w) t += red[w];
        g_cvec[row] = t;
    }
}

// Persistent GRU: 128 blocks, block = (bg: 16b) x (jg: 16j).
// Groups of 32 blocks (same bg) are data-closed: per-group flag barrier.
__global__ __launch_bounds__(256, 1) void gru_kernel(const float* __restrict__ w_hh,
                                                     const float* __restrict__ b_hh) {
    extern __shared__ float sm[];
    float* ws = sm;
    float* hs = ws + 48 * WS_STRIDE;
    float* ps = hs + 16 * WS_STRIDE;
    const int tid = threadIdx.x;
    const int bg = blockIdx.x & 3, jg = blockIdx.x >> 2;
    const int b0 = bg * 16, j0 = jg * 16;
    for (int i = tid; i < 48 * 128; i += 256) {
        int row = i >> 7, k4 = (i & 127) * 4;
        int jj = row / 3, g = row % 3;
        *(float4*)&ws[row * WS_STRIDE + k4] =
            *(const float4*)&w_hh[((size_t)(g * Hh + j0 + jj)) * Hh + k4];
    }
    const int tb = tid & 3, tjg = (tid >> 2) & 15, ks = tid >> 6;
    const int cbb = tid & 15, cjj = tid >> 4;
    const int cb = b0 + cbb, cj = j0 + cjj;
    const float bh0 = b_hh[0 * Hh + cj];
    const float bh1 = b_hh[1 * Hh + cj];
    const float bh2 = b_hh[2 * Hh + cj];
    volatile unsigned* gflags = g_flags;
    for (int t = 0; t < Lsz; ++t) {
        // Prefetch gate inputs (independent of h) before the barrier wait
        const float* xgp = &g_xg[((size_t)cb * Lsz + t) * H3];
        float xr = __ldg(&xgp[cj]);
        float xz = __ldg(&xgp[Hh + cj]);
        float xn = __ldg(&xgp[2 * Hh + cj]);
        // Distributed group barrier: wait for all 32 producers of group bg
        if (t > 0) {
            if (tid < 32) {
                volatile unsigned* f = &gflags[bg * 32 + tid];
                while (*f < (unsigned)t) {}
            }
            __syncthreads();
            __threadfence();
        }
        const float* hsrc = g_h[t & 1];
        for (int i = tid; i < 16 * 128; i += 256) {
            int bb = i >> 7, k4 = (i & 127) * 4;
            float4 v = __ldcg((const float4*)&hsrc[(b0 + bb) * Hh + k4]);
            *(float4*)&hs[bb * WS_STRIDE + k4] = v;
        }
        __syncthreads();
        u64 acc2[3][4];
#pragma unroll
        for (int g = 0; g < 3; ++g)
#pragma unroll
            for (int i = 0; i < 4; ++i) acc2[g][i] = 0ull;
        const int kb = ks * 128;
#pragma unroll 4
        for (int k = kb; k < kb + 128; k += 4) {
            ulonglong2 h2[4];
#pragma unroll
            for (int i = 0; i < 4; ++i)
                h2[i] = *(ulonglong2*)&hs[(i*4 + tb) * WS_STRIDE + k];
#pragma unroll
            for (int g = 0; g < 3; ++g) {
                ulonglong2 w2 = *(ulonglong2*)&ws[(tjg*3 + g) * WS_STRIDE + k];
#pragma unroll
                for (int i = 0; i < 4; ++i) {
                    acc2[g][i] = ffma2(h2[i].x, w2.x, acc2[g][i]);
                    acc2[g][i] = ffma2(h2[i].y, w2.y, acc2[g][i]);
                }
            }
        }
#pragma unroll
        for (int g = 0; g < 3; ++g)
#pragma unroll
            for (int i = 0; i < 4; ++i) {
                F2U v; v.u = acc2[g][i];
                ps[((tjg*3 + g) * 16 + (i*4 + tb)) * 4 + ks] = v.f.x + v.f.y;
            }
        __syncthreads();
        {
            const float* pp0 = &ps[((cjj*3 + 0) * 16 + cbb) * 4];
            const float* pp1 = &ps[((cjj*3 + 1) * 16 + cbb) * 4];
            const float* pp2 = &ps[((cjj*3 + 2) * 16 + cbb) * 4];
            float hg0 = pp0[0] + pp0[1] + pp0[2] + pp0[3] + bh0;
            float hg1 = pp1[0] + pp1[1] + pp1[2] + pp1[3] + bh1;
            float hg2 = pp2[0] + pp2[1] + pp2[2] + pp2[3] + bh2;
            float r = 1.0f / (1.0f + expf(-(xr + hg0)));
            float z = 1.0f / (1.0f + expf(-(xz + hg1)));
            float n = tanhf(xn + r * hg2);
            float hprev = hs[cbb * WS_STRIDE + cj];
            float hnew = (1.0f - z) * n + z * hprev;
            g_h[(t + 1) & 1][cb * Hh + cj] = hnew;
            g_gru[((size_t)cb * Lsz + t) * Hh + cj] = hnew;
        }
        __syncthreads();
        if (tid == 0) {
            __threadfence();
            gflags[bg * 32 + jg] = (unsigned)(t + 1);
        }
    }
}

__global__ void master_kernel(const int* __restrict__ qd) {
    int bt = blockIdx.x, tid = threadIdx.x;
    int k = qd[bt] - 1;
    float4 a = ((const float4*)(g_gru + (size_t)bt * Hh))[tid];
    float4 b = ((const float4*)(g_M2 + (size_t)k * Hh))[tid];
    float s = a.x*b.x + a.y*b.y + a.z*b.z + a.w*b.w;
#pragma unroll
    for (int o = 16; o > 0; o >>= 1) s += __shfl_down_sync(0xffffffffu, s, o);
    __shared__ float red[4];
    if ((tid & 31) == 0) red[tid >> 5] = s;
    __syncthreads();
    if (tid == 0) {
        float got = red[0] + red[1] + red[2] + red[3] + g_cvec[k];
        g_mvals[bt] = (got >= 0.4f) ? 1.0f : got;
    }
}

__global__ __launch_bounds__(256) void dina_kernel(const int* __restrict__ qd,
                                                   const int* __restrict__ qad,
                                                   const float* __restrict__ target,
                                                   float* __restrict__ out, int out_size) {
    __shared__ int qs[Lsz];
    __shared__ float qaS[Lsz], mvS[Lsz], mcS[Lsz], miS[Lsz], nmcS[Lsz], aaS[Lsz];
    __shared__ float guess[Qq], slip[Qq];
    int b = blockIdx.x, tid = threadIdx.x;
    const int off = (out_size >= BL + 2) ? 1 : 0;
    for (int i = tid; i < Qq; i += 256) { guess[i] = 0.f; slip[i] = 0.f; }
    if (tid < Lsz) {
        int bt = b * Lsz + tid;
        int q = qd[bt];
        qs[tid] = q;
        qaS[tid] = (float)((qad[bt] - q) / NQc);
        mvS[tid] = g_mvals[bt];
    }
    __syncthreads();
    if (tid < Lsz) {
        int qt = qs[tid];
        float mc = 0.f, mi = 0.f, nmc = 0.f, aa = 0.f;
        for (int k = 0; k <= tid; ++k) {
            if (qs[k] == qt) {
                aa += 1.f;
                if (k < tid) {
                    float qa1 = qaS[k];
                    float ma = (mvS[k] == 1.f) ? 1.f : 0.f;
                    float nm = (mvS[k] == 0.f) ? 1.f : 0.f;
                    mc += qa1 * ma; mi += (1.f - qa1) * ma; nmc += (1.f - qa1) * nm;
                }
            }
        }
        mcS[tid] = mc; miS[tid] = mi; nmcS[tid] = nmc; aaS[tid] = aa;
    }
    __syncthreads();
    if (tid == 0) {
        float mse = 0.f, cnt = 0.f;
        for (int t = 0; t < Lsz; ++t) {
            int i = qs[t] - 1;
            float m = mvS[t], qa = qaS[t], aa = aaS[t];
            float g_upd = (m == 1.f) ? mcS[t] / aa
                        : ((qa == 0.f) ? 1.f - nmcS[t] / aa : nmcS[t] / aa);
            bool us = (m == 1.f) && (qa == 0.f);
            float ng = us ? guess[i] : g_upd;
            float ns = us ? miS[t] / aa : slip[i];
            guess[i] = ng; slip[i] = ns;
            float p = (1.f - ns) * (m * ng + (1.f - ns) * (1.f - m));
            float lab = target[b * Lsz + t];
            if (lab > -0.9f) { float d = p - lab; mse += d * d; cnt += 1.f; }
            out[off + b * Lsz + t] = 1.f / (1.f + expf(-p));
        }
        atomicAdd(&g_mse, mse);
        atomicAdd(&g_cnt, cnt);
    }
}

__global__ void finalize_kernel(float* __restrict__ out, int out_size) {
    if (threadIdx.x == 0 && out_size >= BL + 2) {
        out[0] = g_mse + 1e-5f * g_creg;
        out[BL + 1] = g_cnt;
    }
}

extern "C" void kernel_launch(void* const* d_in, const int* in_sizes, int n_in,
                              void* d_out, int out_size) {
    const int*   qd     = (const int*)d_in[0];
    const int*   qad    = (const int*)d_in[1];
    const int*   pidd   = (const int*)d_in[2];
    const float* matrix = (const float*)d_in[3];
    const float* target = (const float*)d_in[4];
    const float* q_emb  = (const float*)d_in[5];
    const float* qa_emb = (const float*)d_in[6];
    const float* q_ed   = (const float*)d_in[7];
    const float* qa_ed  = (const float*)d_in[8];
    const float* dparm  = (const float*)d_in[9];
    const float* w_ih   = (const float*)d_in[10];
    const float* w_hh   = (const float*)d_in[11];
    const float* b_ih   = (const float*)d_in[12];
    const float* b_hh   = (const float*)d_in[13];
    const float* fc_w   = (const float*)d_in[14];
    const float* fc_b   = (const float*)d_in[15];
    float* out = (float*)d_out;

    float* dev_P = nullptr; float* dev_R = nullptr;
    cudaGetSymbolAddress((void**)&dev_P, g_P);
    cudaGetSymbolAddress((void**)&dev_R, g_R);

    cudaFuncSetAttribute(gru_kernel, cudaFuncAttributeMaxDynamicSharedMemorySize,
                         (int)GRU_SMEM);

    init_kernel<<<128, 256>>>();
    sgemm_embed<<<dim3(H3 / 128, (NQ1 + 127) / 128), 256>>>(q_emb, w_ih, dev_P, 0);
    sgemm_embed<<<dim3(H3 / 128, (NQ1 + 127) / 128), 256>>>(q_ed, w_ih, dev_R, 1);
    cd_kernel<<<H3 / 8, 256>>>(qa_emb, qa_ed, w_ih);
    xg_build<<<BL, 384>>>(qd, qad, pidd, dparm, b_ih);
    sgemm64_nn<<<dim3(Hh / 64, Qq / 64), 256>>>(matrix, fc_w);
    cvec_kernel<<<Qq, 256>>>(matrix, fc_b);
    gru_kernel<<<128, 256, GRU_SMEM>>>(w_hh, b_hh);
    master_kernel<<<BL, 128>>>(qd);
    dina_kernel<<<Bsz, 256>>>(qd, qad, target, out, out_size);
    finalize_kernel<<<1, 32>>>(out, out_size);
}